// round 2
// baseline (speedup 1.0000x reference)
#include <cuda_runtime.h>
#include <cstddef>

#define NN   64
#define CIN  192
#define TT   256
#define VV   25
#define KK   3
#define COUT 64
#define SS   5
#define OC   192            // K*COUT
#define MM   6400           // T*V

// -------- scratch (__device__ globals are the allowed scratch mechanism) ----
__device__ __align__(16) float g_Y[(size_t)NN * OC * MM];     // 314.6 MB
__device__ __align__(16) float g_ybar[NN * OC * VV];

// -------- packed fp32x2 fma (sm_100+) ---------------------------------------
__device__ __forceinline__ float2 ffma2(float2 a, float2 b, float2 c) {
    float2 d;
    asm("fma.rn.f32x2 %0, %1, %2, %3;"
        : "=l"(reinterpret_cast<unsigned long long&>(d))
        : "l"(reinterpret_cast<unsigned long long const&>(a)),
          "l"(reinterpret_cast<unsigned long long const&>(b)),
          "l"(reinterpret_cast<unsigned long long const&>(c)));
    return d;
}

// ============================================================================
// Stage 1: Y[n,o,m] = sum_c Wc[o,c]*X[n,c,m] + bc[o]
// block tile 64(o) x 128(m), 256 threads, thread tile 4x8, k-chunk 16
// ============================================================================
__global__ __launch_bounds__(256, 2)
void k_gemm(const float* __restrict__ x, const float* __restrict__ Wc,
            const float* __restrict__ bc) {
    __shared__ float sW[16][64];
    __shared__ float sX[16][128];

    const int n   = blockIdx.z;
    const int or0 = blockIdx.y * 64;
    const int c0b = blockIdx.x * 128;
    const float* xn = x + (size_t)n * CIN * MM + c0b;

    const int tid = threadIdx.x;
    const int ty  = tid >> 4;        // 0..15 -> rows r0..r0+3
    const int tx  = tid & 15;        // 0..15 -> cols cc0..cc0+7
    const int r0  = ty * 4;
    const int cc0 = tx * 8;

    float2 acc0[8], acc1[8];
    {
        float2 bA = *(const float2*)(bc + or0 + r0);
        float2 bB = *(const float2*)(bc + or0 + r0 + 2);
#pragma unroll
        for (int c = 0; c < 8; c++) { acc0[c] = bA; acc1[c] = bB; }
    }

    for (int k0 = 0; k0 < CIN; k0 += 16) {
        // load X chunk: 16x128 floats via 2 float4 per thread
#pragma unroll
        for (int i = 0; i < 2; i++) {
            int idx = tid + 256 * i;             // 0..511
            int row = idx >> 5;
            int cg  = (idx & 31) << 2;
            *(float4*)&sX[row][cg] =
                *(const float4*)(xn + (size_t)(k0 + row) * MM + cg);
        }
        // load W chunk: 16x64, transposed scatter
        {
            int o  = tid >> 2;                   // 0..63
            int kq = (tid & 3) << 2;             // 0,4,8,12
            float4 wv = *(const float4*)(Wc + (size_t)(or0 + o) * CIN + k0 + kq);
            sW[kq + 0][o] = wv.x; sW[kq + 1][o] = wv.y;
            sW[kq + 2][o] = wv.z; sW[kq + 3][o] = wv.w;
        }
        __syncthreads();

#pragma unroll
        for (int kk = 0; kk < 16; kk++) {
            float2 wA = *(const float2*)&sW[kk][r0];
            float2 wB = *(const float2*)&sW[kk][r0 + 2];
            float4 xa = *(const float4*)&sX[kk][cc0];
            float4 xb = *(const float4*)&sX[kk][cc0 + 4];
            float xs[8] = {xa.x, xa.y, xa.z, xa.w, xb.x, xb.y, xb.z, xb.w};
#pragma unroll
            for (int c = 0; c < 8; c++) {
                float2 xx = make_float2(xs[c], xs[c]);
                acc0[c] = ffma2(wA, xx, acc0[c]);
                acc1[c] = ffma2(wB, xx, acc1[c]);
            }
        }
        __syncthreads();
    }

    float* yb = g_Y + ((size_t)n * OC + or0 + r0) * MM + c0b + cc0;
#pragma unroll
    for (int j = 0; j < 4; j++) {
        float2* a = (j < 2) ? acc0 : acc1;
        const int hi = j & 1;
        float buf[8];
#pragma unroll
        for (int c = 0; c < 8; c++) buf[c] = hi ? a[c].y : a[c].x;
        float* dst = yb + (size_t)j * MM;
        *(float4*)(dst)     = make_float4(buf[0], buf[1], buf[2], buf[3]);
        *(float4*)(dst + 4) = make_float4(buf[4], buf[5], buf[6], buf[7]);
    }
}

// ============================================================================
// Stage 2: ybar[n,o,v] = mean_t Y[n,o,t,v]
// ============================================================================
__global__ __launch_bounds__(200)
void k_ybar() {
    const int o = blockIdx.x, n = blockIdx.y;
    const float* yp = g_Y + ((size_t)n * OC + o) * MM;
    const int v = threadIdx.x % 25, tg = threadIdx.x / 25;   // tg 0..7
    __shared__ float red[8][25];
    float s = 0.f;
    for (int t = tg; t < TT; t += 8) s += yp[t * VV + v];
    red[tg][v] = s;
    __syncthreads();
    if (threadIdx.x < VV) {
        float a = 0.f;
#pragma unroll
        for (int i = 0; i < 8; i++) a += red[i][threadIdx.x];
        g_ybar[((size_t)n * OC + o) * VV + threadIdx.x] = a * (1.f / TT);
    }
}

// ============================================================================
// Stage 3: graphs[n,s,c,0,0,v] = sem[n,s,c] - x2m[n,s*64+c,v]
//   x{1,2}m = W{1,2} @ ybar + b{1,2};  sem = masked mean over v of x1m
// ============================================================================
__global__ __launch_bounds__(320)
void k_graphs(const float* __restrict__ W1, const float* __restrict__ b1,
              const float* __restrict__ W2, const float* __restrict__ b2,
              const int* __restrict__ node_type, float* __restrict__ gout) {
    const int n = blockIdx.x, o2 = threadIdx.x;   // o2 in [0,320)
    __shared__ float syb[OC * VV];                // 19.2 KB
    __shared__ int   stype[VV];
    __shared__ float sinv[SS];

    for (int i = o2; i < OC * VV; i += 320) syb[i] = g_ybar[(size_t)n * OC * VV + i];
    // node_type may arrive as int32 or int64 (jax x64 coercion) — detect.
    // data is v%5, so int32 layout has node_type[1]==1; int64 layout has 0 there.
    const bool is64 = (node_type[1] == 0);
    if (o2 < VV) stype[o2] = is64 ? node_type[2 * o2] : node_type[o2];
    __syncthreads();
    if (o2 < SS) {
        int cnt = 0;
        for (int v = 0; v < VV; v++) cnt += (stype[v] == o2);
        sinv[o2] = 1.f / (float)cnt;
    }

    float x1m[VV], x2m[VV];
    const float bb1 = b1[o2], bb2 = b2[o2];
#pragma unroll
    for (int v = 0; v < VV; v++) { x1m[v] = bb1; x2m[v] = bb2; }

    const float* w1r = W1 + (size_t)o2 * OC;
    const float* w2r = W2 + (size_t)o2 * OC;
    for (int o = 0; o < OC; o++) {
        const float w1 = w1r[o], w2 = w2r[o];
        const float* yb = &syb[o * VV];
#pragma unroll
        for (int v = 0; v < VV; v++) {
            x1m[v] += w1 * yb[v];
            x2m[v] += w2 * yb[v];
        }
    }
    __syncthreads();   // sinv ready (uniform barrier)

    const int s = o2 / COUT;
    float sem = 0.f;
#pragma unroll
    for (int v = 0; v < VV; v++) if (stype[v] == s) sem += x1m[v];
    sem *= sinv[s];

    float* gp = gout + (size_t)n * (SS * COUT * VV) + (size_t)o2 * VV;
#pragma unroll
    for (int v = 0; v < VV; v++) gp[v] = sem - x2m[v];
}

// ============================================================================
// Stage 4: out[n,c,t,w] = sum_k sum_v Y[n,k*64+c,t,v] * A[k,v,w]
// ============================================================================
__global__ __launch_bounds__(800)
void k_out(const float* __restrict__ A, float* __restrict__ out) {
    __shared__ float sA[KK * VV * VV];   // 1875
    __shared__ float sY[KK][32 * VV];    // 2400
    const int t0 = blockIdx.x * 32;
    const int c  = blockIdx.y;
    const int n  = blockIdx.z;
    const int tid = threadIdx.x;

    for (int i = tid; i < KK * VV * VV; i += 800) sA[i] = A[i];
#pragma unroll
    for (int k = 0; k < KK; k++) {
        const float* yk = g_Y + ((size_t)n * OC + k * COUT + c) * MM + (size_t)t0 * VV;
        sY[k][tid] = yk[tid];
    }
    __syncthreads();

    const int w  = tid % 25;
    const int ty = tid / 25;
    float acc = 0.f;
#pragma unroll
    for (int k = 0; k < KK; k++) {
        const float* yrow = &sY[k][ty * VV];
        const float* arow = &sA[k * VV * VV];
#pragma unroll
        for (int v = 0; v < VV; v++) acc += yrow[v] * arow[v * VV + w];
    }
    out[(((size_t)n * COUT + c) * TT + t0 + ty) * VV + w] = acc;
}

__global__ void k_copyA(const float* __restrict__ A, float* __restrict__ dst) {
    int i = blockIdx.x * 256 + threadIdx.x;
    if (i < KK * VV * VV) dst[i] = A[i];
}

// ============================================================================
extern "C" void kernel_launch(void* const* d_in, const int* in_sizes, int n_in,
                              void* d_out, int out_size) {
    (void)in_sizes; (void)n_in; (void)out_size;
    const float* x  = (const float*)d_in[0];
    const float* A  = (const float*)d_in[1];
    const int*   nt = (const int*)  d_in[2];
    const float* Wc = (const float*)d_in[3];
    const float* bc = (const float*)d_in[4];
    const float* W1 = (const float*)d_in[5];
    const float* b1 = (const float*)d_in[6];
    const float* W2 = (const float*)d_in[7];
    const float* b2 = (const float*)d_in[8];

    float* out  = (float*)d_out;
    float* outA = out + (size_t)NN * COUT * TT * VV;   // 26,214,400
    float* outG = outA + KK * VV * VV;                 // + 1,875

    k_gemm  <<<dim3(50, 3, NN), 256>>>(x, Wc, bc);
    k_ybar  <<<dim3(OC, NN),    200>>>();
    k_graphs<<<NN,              320>>>(W1, b1, W2, b2, nt, outG);
    k_out   <<<dim3(8, COUT, NN), 800>>>(A, out);
    k_copyA <<<8, 256>>>(A, outA);
}

// round 3
// speedup vs baseline: 1.4858x; 1.4858x over previous
#include <cuda_runtime.h>
#include <cstddef>

#define NN   64
#define CIN  192
#define TT   256
#define VV   25
#define KK   3
#define COUT 64
#define SS   5
#define OC   192            // K*COUT
#define MM   6400           // T*V
#define TCH  8              // t's per block
#define MB   200            // cols per block (TCH*VV)
#define NTC  32             // t-chunks (TT/TCH)
#define NTHR 400

// -------- scratch ------------------------------------------------------------
__device__ __align__(16) float g_Wt[CIN * OC];                 // Wc transposed [c][o]
__device__ __align__(16) float g_pt[(size_t)NN * NTC * OC * VV]; // ybar t-partials
__device__ __align__(16) float g_ybar[NN * OC * VV];

// -------- helpers ------------------------------------------------------------
__device__ __forceinline__ float2 ffma2(float2 a, float2 b, float2 c) {
    float2 d;
    asm("fma.rn.f32x2 %0, %1, %2, %3;"
        : "=l"(reinterpret_cast<unsigned long long&>(d))
        : "l"(reinterpret_cast<unsigned long long const&>(a)),
          "l"(reinterpret_cast<unsigned long long const&>(b)),
          "l"(reinterpret_cast<unsigned long long const&>(c)));
    return d;
}
__device__ __forceinline__ void cpasync16(void* dst, const void* src) {
    unsigned s32 = (unsigned)__cvta_generic_to_shared(dst);
    asm volatile("cp.async.cg.shared.global [%0], [%1], 16;" :: "r"(s32), "l"(src));
}
__device__ __forceinline__ void cpcommit() { asm volatile("cp.async.commit_group;"); }
template<int N> __device__ __forceinline__ void cpwait() {
    asm volatile("cp.async.wait_group %0;" :: "n"(N));
}

// smem layout (floats)
#define SY_OFF   0                         // [192][200]
#define SX_OFF   38400                     // 2 x [16][200]
#define SW_OFF   44800                     // 2 x [16][192]
#define SA_OFF   50944                     // [3][25][28]
#define SMEM_FLOATS 53044
#define SMEM_BYTES  (SMEM_FLOATS * 4)

// ============================================================================
// tiny: transpose Wc -> g_Wt[c][o]
// ============================================================================
__global__ void k_wt(const float* __restrict__ Wc) {
    int idx = blockIdx.x * 256 + threadIdx.x;
    if (idx < OC * CIN) {
        int o = idx / CIN, c = idx % CIN;
        g_Wt[c * OC + o] = Wc[idx];
    }
}

// ============================================================================
// fused: GEMM (Y tile in smem) + ybar partials + graph-conv contraction + store
// grid (NTC, NN), block 400
// ============================================================================
__global__ __launch_bounds__(NTHR, 1)
void k_fused(const float* __restrict__ x, const float* __restrict__ bc,
             const float* __restrict__ A, float* __restrict__ out) {
    extern __shared__ float smem[];
    float* sY = smem + SY_OFF;
    float* sA = smem + SA_OFF;     // [3][25][28]

    const int tcb = blockIdx.x;
    const int n   = blockIdx.y;
    const int tid = threadIdx.x;
    const float* xn = x + (size_t)n * CIN * MM + (size_t)tcb * MB;

    // ---- sA fill: sA[k][v][w] = A[k*625 + v*25 + w], row stride 28 ----
    for (int i = tid; i < KK * VV * VV; i += NTHR) {
        int k = i / (VV * VV), r = i % (VV * VV);
        sA[(k * VV + r / VV) * 28 + (r % VV)] = A[i];
    }

    // ---- GEMM thread mapping ----
    const int rg  = tid / 25;        // 0..15
    const int cg  = tid % 25;        // 0..24
    const int rg4 = rg * 4;
    const int cg8 = cg * 8;

    float2 accA[3][8], accB[3][8];
#pragma unroll
    for (int p = 0; p < 3; p++) {
        float2 bA = *(const float2*)(bc + p * 64 + rg4);
        float2 bB = *(const float2*)(bc + p * 64 + rg4 + 2);
#pragma unroll
        for (int c = 0; c < 8; c++) { accA[p][c] = bA; accB[p][c] = bB; }
    }

    // async loaders (per k-chunk of 16)
    auto loadX = [&](int buf, int k0) {
        float* dst = smem + SX_OFF + buf * 3200;
#pragma unroll
        for (int i = 0; i < 2; i++) {
            int q = tid + NTHR * i;                 // 0..799
            int row = q / 50, c4 = (q % 50) * 4;
            cpasync16(dst + row * MB + c4, xn + (size_t)(k0 + row) * MM + c4);
        }
    };
    auto loadW = [&](int buf, int k0) {
        float* dst = smem + SW_OFF + buf * 3072;
#pragma unroll
        for (int i = 0; i < 2; i++) {
            int q = tid + NTHR * i;                 // 0..799, need <768
            if (q < 768) {
                int row = q / 48, c4 = (q % 48) * 4;
                cpasync16(dst + row * OC + c4, g_Wt + (size_t)(k0 + row) * OC + c4);
            }
        }
    };

    loadX(0, 0); loadW(0, 0); cpcommit();

    for (int kc = 0; kc < 12; kc++) {
        const int buf = kc & 1;
        if (kc < 11) { loadX(buf ^ 1, (kc + 1) * 16); loadW(buf ^ 1, (kc + 1) * 16); cpcommit(); }
        if (kc < 11) cpwait<1>(); else cpwait<0>();
        __syncthreads();

        const float* sX = smem + SX_OFF + buf * 3200;
        const float* sW = smem + SW_OFF + buf * 3072;
#pragma unroll
        for (int kk = 0; kk < 16; kk++) {
            const float4 xa = *(const float4*)&sX[kk * MB + cg8];
            const float4 xb = *(const float4*)&sX[kk * MB + cg8 + 4];
            const float xs[8] = {xa.x, xa.y, xa.z, xa.w, xb.x, xb.y, xb.z, xb.w};
#pragma unroll
            for (int p = 0; p < 3; p++) {
                const float2 wA = *(const float2*)&sW[kk * OC + p * 64 + rg4];
                const float2 wB = *(const float2*)&sW[kk * OC + p * 64 + rg4 + 2];
#pragma unroll
                for (int c = 0; c < 8; c++) {
                    float2 xx = make_float2(xs[c], xs[c]);
                    accA[p][c] = ffma2(wA, xx, accA[p][c]);
                    accB[p][c] = ffma2(wB, xx, accB[p][c]);
                }
            }
        }
        __syncthreads();
    }

    // ---- write Y tile to smem ----
#pragma unroll
    for (int p = 0; p < 3; p++) {
        float* r0 = &sY[(p * 64 + rg4 + 0) * MB + cg8];
        float* r1 = &sY[(p * 64 + rg4 + 1) * MB + cg8];
        float* r2 = &sY[(p * 64 + rg4 + 2) * MB + cg8];
        float* r3 = &sY[(p * 64 + rg4 + 3) * MB + cg8];
        *(float4*)(r0)     = make_float4(accA[p][0].x, accA[p][1].x, accA[p][2].x, accA[p][3].x);
        *(float4*)(r0 + 4) = make_float4(accA[p][4].x, accA[p][5].x, accA[p][6].x, accA[p][7].x);
        *(float4*)(r1)     = make_float4(accA[p][0].y, accA[p][1].y, accA[p][2].y, accA[p][3].y);
        *(float4*)(r1 + 4) = make_float4(accA[p][4].y, accA[p][5].y, accA[p][6].y, accA[p][7].y);
        *(float4*)(r2)     = make_float4(accB[p][0].x, accB[p][1].x, accB[p][2].x, accB[p][3].x);
        *(float4*)(r2 + 4) = make_float4(accB[p][4].x, accB[p][5].x, accB[p][6].x, accB[p][7].x);
        *(float4*)(r3)     = make_float4(accB[p][0].y, accB[p][1].y, accB[p][2].y, accB[p][3].y);
        *(float4*)(r3 + 4) = make_float4(accB[p][4].y, accB[p][5].y, accB[p][6].y, accB[p][7].y);
    }
    __syncthreads();

    // ---- ybar t-partials ----
    {
        float* pt = g_pt + ((size_t)n * NTC + tcb) * (OC * VV);
        for (int idx = tid; idx < OC * VV; idx += NTHR) {
            int o = idx / VV, v = idx % VV;
            const float* yr = &sY[o * MB + v];
            float s = 0.f;
#pragma unroll
            for (int t = 0; t < TCH; t++) s += yr[t * VV];
            pt[idx] = s;
        }
    }

    // ---- graph-conv contraction: acc[pair][w] = sum_k sum_v Y[k*64+c][t*25+v]*A[k,v,w]
    float2 accO[2][12];
    float  accL[2] = {0.f, 0.f};
#pragma unroll
    for (int cc = 0; cc < 2; cc++)
#pragma unroll
        for (int j = 0; j < 12; j++) accO[cc][j] = make_float2(0.f, 0.f);

    const int pair0 = tid, pair1 = tid + NTHR;
    const bool has1 = (pair1 < 512);
    const int yb0 = pair0 * 25;     // c*200 + t*25 == 25*pair
    const int yb1 = pair1 * 25;

#pragma unroll
    for (int k = 0; k < KK; k++) {
        const int kof = k * 64 * MB;
#pragma unroll
        for (int v = 0; v < VV; v++) {
            const float4* ap = (const float4*)&sA[(k * VV + v) * 28];
            const float4 a0 = ap[0], a1 = ap[1], a2 = ap[2],
                         a3 = ap[3], a4 = ap[4], a5 = ap[5];
            const float  aL = sA[(k * VV + v) * 28 + 24];
            const float2 af[12] = {
                {a0.x,a0.y},{a0.z,a0.w},{a1.x,a1.y},{a1.z,a1.w},
                {a2.x,a2.y},{a2.z,a2.w},{a3.x,a3.y},{a3.z,a3.w},
                {a4.x,a4.y},{a4.z,a4.w},{a5.x,a5.y},{a5.z,a5.w}};
            {
                const float y = sY[kof + yb0 + v];
                const float2 yy = make_float2(y, y);
#pragma unroll
                for (int j = 0; j < 12; j++) accO[0][j] = ffma2(af[j], yy, accO[0][j]);
                accL[0] += y * aL;
            }
            if (has1) {
                const float y = sY[kof + yb1 + v];
                const float2 yy = make_float2(y, y);
#pragma unroll
                for (int j = 0; j < 12; j++) accO[1][j] = ffma2(af[j], yy, accO[1][j]);
                accL[1] += y * aL;
            }
        }
    }
    __syncthreads();     // all sY reads done; reuse sY as output staging

    // ---- stage results (layout: pair*25 + w  ==  c*200 + t*25 + w) ----
#pragma unroll
    for (int cc = 0; cc < 2; cc++) {
        int pair = (cc == 0) ? pair0 : pair1;
        if (pair < 512) {
            float* st = &sY[pair * 25];
#pragma unroll
            for (int j = 0; j < 12; j++) { st[2*j] = accO[cc][j].x; st[2*j+1] = accO[cc][j].y; }
            st[24] = accL[cc];
        }
    }
    __syncthreads();

    // ---- coalesced copy to global ----
    float* ob = out + (size_t)n * COUT * MM + (size_t)tcb * MB;
    for (int i = tid; i < COUT * MB; i += NTHR) {
        int c = i / MB, j = i % MB;
        ob[(size_t)c * MM + j] = sY[i];
    }
}

// ============================================================================
// reduce ybar partials
// ============================================================================
__global__ __launch_bounds__(256)
void k_ybar_reduce() {
    const int n = blockIdx.x;
    for (int idx = threadIdx.x; idx < OC * VV; idx += 256) {
        float s = 0.f;
#pragma unroll 4
        for (int tc = 0; tc < NTC; tc++)
            s += g_pt[((size_t)n * NTC + tc) * (OC * VV) + idx];
        g_ybar[(size_t)n * OC * VV + idx] = s * (1.f / TT);
    }
}

// ============================================================================
// graphs (unchanged from passing round)
// ============================================================================
__global__ __launch_bounds__(320)
void k_graphs(const float* __restrict__ W1, const float* __restrict__ b1,
              const float* __restrict__ W2, const float* __restrict__ b2,
              const int* __restrict__ node_type, float* __restrict__ gout) {
    const int n = blockIdx.x, o2 = threadIdx.x;
    __shared__ float syb[OC * VV];
    __shared__ int   stype[VV];
    __shared__ float sinv[SS];

    for (int i = o2; i < OC * VV; i += 320) syb[i] = g_ybar[(size_t)n * OC * VV + i];
    const bool is64 = (node_type[1] == 0);
    if (o2 < VV) stype[o2] = is64 ? node_type[2 * o2] : node_type[o2];
    __syncthreads();
    if (o2 < SS) {
        int cnt = 0;
        for (int v = 0; v < VV; v++) cnt += (stype[v] == o2);
        sinv[o2] = 1.f / (float)cnt;
    }

    float x1m[VV], x2m[VV];
    const float bb1 = b1[o2], bb2 = b2[o2];
#pragma unroll
    for (int v = 0; v < VV; v++) { x1m[v] = bb1; x2m[v] = bb2; }

    const float* w1r = W1 + (size_t)o2 * OC;
    const float* w2r = W2 + (size_t)o2 * OC;
    for (int o = 0; o < OC; o++) {
        const float w1 = w1r[o], w2 = w2r[o];
        const float* yb = &syb[o * VV];
#pragma unroll
        for (int v = 0; v < VV; v++) {
            x1m[v] += w1 * yb[v];
            x2m[v] += w2 * yb[v];
        }
    }
    __syncthreads();

    const int s = o2 / COUT;
    float sem = 0.f;
#pragma unroll
    for (int v = 0; v < VV; v++) if (stype[v] == s) sem += x1m[v];
    sem *= sinv[s];

    float* gp = gout + (size_t)n * (SS * COUT * VV) + (size_t)o2 * VV;
#pragma unroll
    for (int v = 0; v < VV; v++) gp[v] = sem - x2m[v];
}

__global__ void k_copyA(const float* __restrict__ A, float* __restrict__ dst) {
    int i = blockIdx.x * 256 + threadIdx.x;
    if (i < KK * VV * VV) dst[i] = A[i];
}

// ============================================================================
extern "C" void kernel_launch(void* const* d_in, const int* in_sizes, int n_in,
                              void* d_out, int out_size) {
    (void)in_sizes; (void)n_in; (void)out_size;
    const float* x  = (const float*)d_in[0];
    const float* A  = (const float*)d_in[1];
    const int*   nt = (const int*)  d_in[2];
    const float* Wc = (const float*)d_in[3];
    const float* bc = (const float*)d_in[4];
    const float* W1 = (const float*)d_in[5];
    const float* b1 = (const float*)d_in[6];
    const float* W2 = (const float*)d_in[7];
    const float* b2 = (const float*)d_in[8];

    float* out  = (float*)d_out;
    float* outA = out + (size_t)NN * COUT * TT * VV;   // 26,214,400
    float* outG = outA + KK * VV * VV;                 // + 1,875

    static int smem_set = 0;
    if (!smem_set) {
        cudaFuncSetAttribute(k_fused, cudaFuncAttributeMaxDynamicSharedMemorySize, SMEM_BYTES);
        smem_set = 1;
    }

    k_wt         <<<(OC * CIN + 255) / 256, 256>>>(Wc);
    k_fused      <<<dim3(NTC, NN), NTHR, SMEM_BYTES>>>(x, bc, A, out);
    k_ybar_reduce<<<NN, 256>>>();
    k_graphs     <<<NN, 320>>>(W1, b1, W2, b2, nt, outG);
    k_copyA      <<<8, 256>>>(A, outA);
}

// round 4
// speedup vs baseline: 1.7340x; 1.1670x over previous
#include <cuda_runtime.h>
#include <cstddef>

#define NN   64
#define CIN  192
#define TT   256
#define VV   25
#define KK   3
#define COUT 64
#define SS   5
#define OC   192            // K*COUT
#define MM   6400           // T*V
#define TCH  4              // t's per block
#define MB   100            // cols per block (TCH*VV)
#define NTC  64             // t-chunks (TT/TCH)
#define NTHR 300
#define KCH  8              // k chunk
#define NKC  (CIN / KCH)    // 24 chunks

// -------- scratch ------------------------------------------------------------
__device__ __align__(16) float g_Wt[CIN * OC];                    // Wc^T [c][o]
__device__ __align__(16) float g_pt[(size_t)NN * NTC * OC * VV];  // ybar t-partials
__device__ __align__(16) float g_ybar[NN * OC * VV];

// -------- helpers ------------------------------------------------------------
__device__ __forceinline__ float2 ffma2(float2 a, float2 b, float2 c) {
    float2 d;
    asm("fma.rn.f32x2 %0, %1, %2, %3;"
        : "=l"(reinterpret_cast<unsigned long long&>(d))
        : "l"(reinterpret_cast<unsigned long long const&>(a)),
          "l"(reinterpret_cast<unsigned long long const&>(b)),
          "l"(reinterpret_cast<unsigned long long const&>(c)));
    return d;
}
__device__ __forceinline__ void cpasync16(void* dst, const void* src) {
    unsigned s32 = (unsigned)__cvta_generic_to_shared(dst);
    asm volatile("cp.async.cg.shared.global [%0], [%1], 16;" :: "r"(s32), "l"(src));
}
__device__ __forceinline__ void cpcommit() { asm volatile("cp.async.commit_group;"); }
template<int N> __device__ __forceinline__ void cpwait() {
    asm volatile("cp.async.wait_group %0;" :: "n"(N));
}

// smem layout (floats)
#define SY_OFF   0                          // [192][100] = 19200
#define SX_OFF   19200                      // 2 x [8][100] = 1600
#define SW_OFF   20800                      // 2 x [8][192] = 3072
#define SA_OFF   23872                      // [3][25][28]  = 2100
#define SMEM_FLOATS 25972
#define SMEM_BYTES  (SMEM_FLOATS * 4)       // 103,888 B -> 2 blocks/SM

// ============================================================================
__global__ void k_wt(const float* __restrict__ Wc) {
    int idx = blockIdx.x * 256 + threadIdx.x;
    if (idx < OC * CIN) {
        int o = idx / CIN, c = idx % CIN;
        g_Wt[c * OC + o] = Wc[idx];
    }
}

// ============================================================================
// fused: GEMM (Y tile in smem) + ybar partials + graph contraction + store
// grid (NTC, NN), block 300, 2 blocks/SM
// ============================================================================
__global__ __launch_bounds__(NTHR, 2)
void k_fused(const float* __restrict__ x, const float* __restrict__ bc,
             const float* __restrict__ A, float* __restrict__ out) {
    extern __shared__ float smem[];
    float* sY = smem + SY_OFF;
    float* sA = smem + SA_OFF;     // [3][25][28]

    const int tcb = blockIdx.x;
    const int n   = blockIdx.y;
    const int tid = threadIdx.x;
    const float* xn = x + (size_t)n * CIN * MM + (size_t)tcb * MB;

    // ---- sA fill ----
    for (int i = tid; i < KK * VV * VV; i += NTHR) {
        int k = i / (VV * VV), r = i % (VV * VV);
        sA[(k * VV + r / VV) * 28 + (r % VV)] = A[i];
    }

    // ---- GEMM thread mapping: 16 rows x 4 cols per thread ----
    const int rg   = tid / 25;       // 0..11 -> rows rg*16..+15
    const int cg   = tid % 25;       // 0..24 -> cols cg*4..+3
    const int rg16 = rg * 16;
    const int cg4  = cg * 4;

    float2 acc[8][4];
#pragma unroll
    for (int p = 0; p < 8; p++) {
        const float2 bp = *(const float2*)(bc + rg16 + 2 * p);
#pragma unroll
        for (int c = 0; c < 4; c++) acc[p][c] = bp;
    }

    // async loaders: X chunk 8x100 (200 float4), W chunk 8x192 (384 float4)
    auto loadX = [&](int buf, int k0) {
        if (tid < 200) {
            float* dst = smem + SX_OFF + buf * 800;
            int row = tid / 25, c4 = (tid % 25) * 4;
            cpasync16(dst + row * MB + c4, xn + (size_t)(k0 + row) * MM + c4);
        }
    };
    auto loadW = [&](int buf, int k0) {
        float* dst = smem + SW_OFF + buf * 1536;
#pragma unroll
        for (int i = 0; i < 2; i++) {
            int q = tid + NTHR * i;
            if (q < 384) {
                int row = q / 48, c4 = (q % 48) * 4;
                cpasync16(dst + row * OC + c4, g_Wt + (size_t)(k0 + row) * OC + c4);
            }
        }
    };

    loadX(0, 0); loadW(0, 0); cpcommit();

    for (int kc = 0; kc < NKC; kc++) {
        const int buf = kc & 1;
        if (kc < NKC - 1) { loadX(buf ^ 1, (kc + 1) * KCH); loadW(buf ^ 1, (kc + 1) * KCH); cpcommit(); }
        if (kc < NKC - 1) cpwait<1>(); else cpwait<0>();
        __syncthreads();

        const float* sX = smem + SX_OFF + buf * 800;
        const float* sW = smem + SW_OFF + buf * 1536;
#pragma unroll
        for (int kk = 0; kk < KCH; kk++) {
            const float4 xv = *(const float4*)&sX[kk * MB + cg4];
            const float xs[4] = {xv.x, xv.y, xv.z, xv.w};
#pragma unroll
            for (int p = 0; p < 8; p++) {
                const float2 w = *(const float2*)&sW[kk * OC + rg16 + 2 * p];
#pragma unroll
                for (int c = 0; c < 4; c++)
                    acc[p][c] = ffma2(w, make_float2(xs[c], xs[c]), acc[p][c]);
            }
        }
        __syncthreads();
    }

    // ---- write Y tile to smem ----
#pragma unroll
    for (int p = 0; p < 8; p++) {
        float* r0 = &sY[(rg16 + 2 * p) * MB + cg4];
        float* r1 = r0 + MB;
        *(float4*)r0 = make_float4(acc[p][0].x, acc[p][1].x, acc[p][2].x, acc[p][3].x);
        *(float4*)r1 = make_float4(acc[p][0].y, acc[p][1].y, acc[p][2].y, acc[p][3].y);
    }
    __syncthreads();

    // ---- ybar t-partials ----
    {
        float* pt = g_pt + ((size_t)n * NTC + tcb) * (OC * VV);
        for (int idx = tid; idx < OC * VV; idx += NTHR) {
            int o = idx / VV, v = idx % VV;
            const float* yr = &sY[o * MB + v];
            float s = 0.f;
#pragma unroll
            for (int t = 0; t < TCH; t++) s += yr[t * VV];
            pt[idx] = s;
        }
    }

    // ---- graph contraction: pair = c*TCH + t  (256 pairs, threads 0..255) ----
    float2 accO[12];
    float  accL = 0.f;
#pragma unroll
    for (int j = 0; j < 12; j++) accO[j] = make_float2(0.f, 0.f);

    const bool work = (tid < COUT * TCH);
    const int ybase = tid * VV;              // c*100 + t*25

    if (work) {
#pragma unroll
        for (int k = 0; k < KK; k++) {
            const int kof = k * COUT * MB;
#pragma unroll
            for (int v = 0; v < VV; v++) {
                const float4* ap = (const float4*)&sA[(k * VV + v) * 28];
                const float4 a0 = ap[0], a1 = ap[1], a2 = ap[2],
                             a3 = ap[3], a4 = ap[4], a5 = ap[5];
                const float  aL = sA[(k * VV + v) * 28 + 24];
                const float y = sY[kof + ybase + v];
                const float2 yy = make_float2(y, y);
                const float2 af[12] = {
                    {a0.x,a0.y},{a0.z,a0.w},{a1.x,a1.y},{a1.z,a1.w},
                    {a2.x,a2.y},{a2.z,a2.w},{a3.x,a3.y},{a3.z,a3.w},
                    {a4.x,a4.y},{a4.z,a4.w},{a5.x,a5.y},{a5.z,a5.w}};
#pragma unroll
                for (int j = 0; j < 12; j++) accO[j] = ffma2(af[j], yy, accO[j]);
                accL += y * aL;
            }
        }
    }
    __syncthreads();     // sY reads done; reuse sY as staging

    if (work) {
        float* st = &sY[tid * VV];
#pragma unroll
        for (int j = 0; j < 12; j++) { st[2*j] = accO[j].x; st[2*j+1] = accO[j].y; }
        st[24] = accL;
    }
    __syncthreads();

    // ---- coalesced copy to global ----
    float* ob = out + (size_t)n * COUT * MM + (size_t)tcb * MB;
    for (int i = tid; i < COUT * MB; i += NTHR) {
        int c = i / MB, j = i % MB;
        ob[(size_t)c * MM + j] = sY[i];
    }
}

// ============================================================================
__global__ __launch_bounds__(256)
void k_ybar_reduce() {
    const int n = blockIdx.x;
    for (int idx = threadIdx.x; idx < OC * VV; idx += 256) {
        float s = 0.f;
#pragma unroll 4
        for (int tc = 0; tc < NTC; tc++)
            s += g_pt[((size_t)n * NTC + tc) * (OC * VV) + idx];
        g_ybar[(size_t)n * OC * VV + idx] = s * (1.f / TT);
    }
}

// ============================================================================
// graphs: grid (NN, SS), 64 threads; all threads in a block share s=blockIdx.y
// ============================================================================
__global__ __launch_bounds__(64)
void k_graphs(const float* __restrict__ W1, const float* __restrict__ b1,
              const float* __restrict__ W2, const float* __restrict__ b2,
              const int* __restrict__ node_type, float* __restrict__ gout) {
    const int n = blockIdx.x, s = blockIdx.y;
    const int o2 = s * COUT + threadIdx.x;
    __shared__ float syb[OC * VV];
    __shared__ int   stype[VV];

    for (int i = threadIdx.x; i < OC * VV; i += 64)
        syb[i] = g_ybar[(size_t)n * OC * VV + i];
    const bool is64 = (node_type[1] == 0);
    if (threadIdx.x < VV)
        stype[threadIdx.x] = is64 ? node_type[2 * threadIdx.x] : node_type[threadIdx.x];
    __syncthreads();

    float x1m[VV], x2m[VV];
    const float bb1 = b1[o2], bb2 = b2[o2];
#pragma unroll
    for (int v = 0; v < VV; v++) { x1m[v] = bb1; x2m[v] = bb2; }

    const float* w1r = W1 + (size_t)o2 * OC;
    const float* w2r = W2 + (size_t)o2 * OC;
    for (int o = 0; o < OC; o++) {
        const float w1 = w1r[o], w2 = w2r[o];
        const float* yb = &syb[o * VV];
#pragma unroll
        for (int v = 0; v < VV; v++) {
            x1m[v] += w1 * yb[v];
            x2m[v] += w2 * yb[v];
        }
    }

    int cnt = 0;
    float sem = 0.f;
#pragma unroll
    for (int v = 0; v < VV; v++) {
        if (stype[v] == s) { sem += x1m[v]; cnt++; }
    }
    sem *= (1.f / (float)cnt);

    float* gp = gout + (size_t)n * (SS * COUT * VV) + (size_t)o2 * VV;
#pragma unroll
    for (int v = 0; v < VV; v++) gp[v] = sem - x2m[v];
}

__global__ void k_copyA(const float* __restrict__ A, float* __restrict__ dst) {
    int i = blockIdx.x * 256 + threadIdx.x;
    if (i < KK * VV * VV) dst[i] = A[i];
}

// ============================================================================
extern "C" void kernel_launch(void* const* d_in, const int* in_sizes, int n_in,
                              void* d_out, int out_size) {
    (void)in_sizes; (void)n_in; (void)out_size;
    const float* x  = (const float*)d_in[0];
    const float* A  = (const float*)d_in[1];
    const int*   nt = (const int*)  d_in[2];
    const float* Wc = (const float*)d_in[3];
    const float* bc = (const float*)d_in[4];
    const float* W1 = (const float*)d_in[5];
    const float* b1 = (const float*)d_in[6];
    const float* W2 = (const float*)d_in[7];
    const float* b2 = (const float*)d_in[8];

    float* out  = (float*)d_out;
    float* outA = out + (size_t)NN * COUT * TT * VV;   // 26,214,400
    float* outG = outA + KK * VV * VV;                 // + 1,875

    static int smem_set = 0;
    if (!smem_set) {
        cudaFuncSetAttribute(k_fused, cudaFuncAttributeMaxDynamicSharedMemorySize, SMEM_BYTES);
        smem_set = 1;
    }

    k_wt         <<<(OC * CIN + 255) / 256, 256>>>(Wc);
    k_fused      <<<dim3(NTC, NN), NTHR, SMEM_BYTES>>>(x, bc, A, out);
    k_ybar_reduce<<<NN, 256>>>();
    k_graphs     <<<dim3(NN, SS), 64>>>(W1, b1, W2, b2, nt, outG);
    k_copyA      <<<8, 256>>>(A, outA);
}

// round 5
// speedup vs baseline: 1.7989x; 1.0374x over previous
#include <cuda_runtime.h>
#include <cstddef>

#define NN   64
#define CIN  192
#define TT   256
#define VV   25
#define KK   3
#define COUT 64
#define SS   5
#define OC   192            // K*COUT
#define MM   6400           // T*V
#define TCH  4              // t's per block
#define MB   100            // cols per block (TCH*VV)
#define NTC  64             // t-chunks (TT/TCH)
#define NTHR 300
#define KCH  8              // k chunk
#define NKC  (CIN / KCH)    // 24 chunks

// -------- scratch ------------------------------------------------------------
__device__ __align__(16) float g_Wt[CIN * OC];                    // Wc^T [c][o]
__device__ __align__(16) float g_pt[(size_t)NN * NTC * OC * VV];  // ybar t-partials
__device__ __align__(16) float g_ybar[NN * OC * VV];

// -------- helpers ------------------------------------------------------------
__device__ __forceinline__ float2 ffma2(float2 a, float2 b, float2 c) {
    float2 d;
    asm("fma.rn.f32x2 %0, %1, %2, %3;"
        : "=l"(reinterpret_cast<unsigned long long&>(d))
        : "l"(reinterpret_cast<unsigned long long const&>(a)),
          "l"(reinterpret_cast<unsigned long long const&>(b)),
          "l"(reinterpret_cast<unsigned long long const&>(c)));
    return d;
}
__device__ __forceinline__ void cpasync16(void* dst, const void* src) {
    unsigned s32 = (unsigned)__cvta_generic_to_shared(dst);
    asm volatile("cp.async.cg.shared.global [%0], [%1], 16;" :: "r"(s32), "l"(src));
}
__device__ __forceinline__ void cpcommit() { asm volatile("cp.async.commit_group;"); }
template<int N> __device__ __forceinline__ void cpwait() {
    asm volatile("cp.async.wait_group %0;" :: "n"(N));
}

// smem layout (floats)
#define SY_OFF   0                          // [192][100] = 19200
#define SX_OFF   19200                      // 2 x [8][100] = 1600
#define SW_OFF   20800                      // 2 x [8][192] = 3072
#define SA_OFF   23872                      // [3][25][28]  = 2100
#define SMEM_FLOATS 25972
#define SMEM_BYTES  (SMEM_FLOATS * 4)       // 103,888 B -> 2 blocks/SM

// ============================================================================
__global__ void k_wt(const float* __restrict__ Wc) {
    int idx = blockIdx.x * 256 + threadIdx.x;
    if (idx < OC * CIN) {
        int o = idx / CIN, c = idx % CIN;
        g_Wt[c * OC + o] = Wc[idx];
    }
}

// ============================================================================
// fused: GEMM (Y tile in smem) + ybar partials + graph contraction + store
// grid (NTC, NN), block 300, 2 blocks/SM
// ============================================================================
__global__ __launch_bounds__(NTHR, 2)
void k_fused(const float* __restrict__ x, const float* __restrict__ bc,
             const float* __restrict__ A, float* __restrict__ out) {
    extern __shared__ float smem[];
    float* sY = smem + SY_OFF;
    float* sA = smem + SA_OFF;     // [3][25][28]

    const int tcb = blockIdx.x;
    const int n   = blockIdx.y;
    const int tid = threadIdx.x;
    const float* xn = x + (size_t)n * CIN * MM + (size_t)tcb * MB;

    // ---- sA fill ----
    for (int i = tid; i < KK * VV * VV; i += NTHR) {
        int k = i / (VV * VV), r = i % (VV * VV);
        sA[(k * VV + r / VV) * 28 + (r % VV)] = A[i];
    }

    // ---- GEMM thread mapping: 16 rows x 4 cols per thread ----
    const int rg   = tid / 25;       // 0..11 -> rows rg*16..+15
    const int cg   = tid % 25;       // 0..24 -> cols cg*4..+3
    const int rg16 = rg * 16;
    const int cg4  = cg * 4;

    float2 acc[8][4];
#pragma unroll
    for (int p = 0; p < 8; p++) {
        const float2 bp = *(const float2*)(bc + rg16 + 2 * p);
#pragma unroll
        for (int c = 0; c < 4; c++) acc[p][c] = bp;
    }

    // async loaders: X chunk 8x100 (200 float4), W chunk 8x192 (384 float4)
    auto loadX = [&](int buf, int k0) {
        if (tid < 200) {
            float* dst = smem + SX_OFF + buf * 800;
            int row = tid / 25, c4 = (tid % 25) * 4;
            cpasync16(dst + row * MB + c4, xn + (size_t)(k0 + row) * MM + c4);
        }
    };
    auto loadW = [&](int buf, int k0) {
        float* dst = smem + SW_OFF + buf * 1536;
#pragma unroll
        for (int i = 0; i < 2; i++) {
            int q = tid + NTHR * i;
            if (q < 384) {
                int row = q / 48, c4 = (q % 48) * 4;
                cpasync16(dst + row * OC + c4, g_Wt + (size_t)(k0 + row) * OC + c4);
            }
        }
    };

    loadX(0, 0); loadW(0, 0); cpcommit();

    for (int kc = 0; kc < NKC; kc++) {
        const int buf = kc & 1;
        cpwait<0>();
        __syncthreads();   // chunk kc visible to all; all done computing buf^1
        if (kc + 1 < NKC) {
            loadX(buf ^ 1, (kc + 1) * KCH);
            loadW(buf ^ 1, (kc + 1) * KCH);
            cpcommit();
        }

        const float* sX = smem + SX_OFF + buf * 800;
        const float* sW = smem + SW_OFF + buf * 1536;
#pragma unroll
        for (int kk = 0; kk < KCH; kk++) {
            const float4 xv = *(const float4*)&sX[kk * MB + cg4];
            const float2 xx[4] = {{xv.x, xv.x}, {xv.y, xv.y}, {xv.z, xv.z}, {xv.w, xv.w}};
#pragma unroll
            for (int q = 0; q < 4; q++) {
                const float4 wv = *(const float4*)&sW[kk * OC + rg16 + 4 * q];
                const float2 wA = {wv.x, wv.y};
                const float2 wB = {wv.z, wv.w};
#pragma unroll
                for (int c = 0; c < 4; c++) {
                    acc[2 * q][c]     = ffma2(wA, xx[c], acc[2 * q][c]);
                    acc[2 * q + 1][c] = ffma2(wB, xx[c], acc[2 * q + 1][c]);
                }
            }
        }
    }
    __syncthreads();

    // ---- write Y tile to smem ----
#pragma unroll
    for (int p = 0; p < 8; p++) {
        float* r0 = &sY[(rg16 + 2 * p) * MB + cg4];
        float* r1 = r0 + MB;
        *(float4*)r0 = make_float4(acc[p][0].x, acc[p][1].x, acc[p][2].x, acc[p][3].x);
        *(float4*)r1 = make_float4(acc[p][0].y, acc[p][1].y, acc[p][2].y, acc[p][3].y);
    }
    __syncthreads();

    // ---- ybar t-partials ----
    {
        float* pt = g_pt + ((size_t)n * NTC + tcb) * (OC * VV);
        for (int idx = tid; idx < OC * VV; idx += NTHR) {
            int o = idx / VV, v = idx % VV;
            const float* yr = &sY[o * MB + v];
            float s = 0.f;
#pragma unroll
            for (int t = 0; t < TCH; t++) s += yr[t * VV];
            pt[idx] = s;
        }
    }

    // ---- graph contraction: pair = c*TCH + t  (256 pairs, threads 0..255) ----
    float2 accO[12];
    float  accL = 0.f;
#pragma unroll
    for (int j = 0; j < 12; j++) accO[j] = make_float2(0.f, 0.f);

    const bool work = (tid < COUT * TCH);
    const int ybase = tid * VV;              // c*100 + t*25

    if (work) {
#pragma unroll
        for (int k = 0; k < KK; k++) {
            const int kof = k * COUT * MB;
#pragma unroll
            for (int v = 0; v < VV; v++) {
                const float4* ap = (const float4*)&sA[(k * VV + v) * 28];
                const float4 a0 = ap[0], a1 = ap[1], a2 = ap[2],
                             a3 = ap[3], a4 = ap[4], a5 = ap[5];
                const float  aL = sA[(k * VV + v) * 28 + 24];
                const float y = sY[kof + ybase + v];
                const float2 yy = make_float2(y, y);
                const float2 af[12] = {
                    {a0.x,a0.y},{a0.z,a0.w},{a1.x,a1.y},{a1.z,a1.w},
                    {a2.x,a2.y},{a2.z,a2.w},{a3.x,a3.y},{a3.z,a3.w},
                    {a4.x,a4.y},{a4.z,a4.w},{a5.x,a5.y},{a5.z,a5.w}};
#pragma unroll
                for (int j = 0; j < 12; j++) accO[j] = ffma2(af[j], yy, accO[j]);
                accL += y * aL;
            }
        }
    }
    __syncthreads();     // sY reads done; reuse sY as staging

    if (work) {
        float* st = &sY[tid * VV];
#pragma unroll
        for (int j = 0; j < 12; j++) { st[2*j] = accO[j].x; st[2*j+1] = accO[j].y; }
        st[24] = accL;
    }
    __syncthreads();

    // ---- coalesced copy to global ----
    float* ob = out + (size_t)n * COUT * MM + (size_t)tcb * MB;
    for (int i = tid; i < COUT * MB; i += NTHR) {
        int c = i / MB, j = i % MB;
        ob[(size_t)c * MM + j] = sY[i];
    }
}

// ============================================================================
__global__ __launch_bounds__(256)
void k_ybar_reduce() {
    const int n = blockIdx.x;
    for (int idx = threadIdx.x; idx < OC * VV; idx += 256) {
        float s = 0.f;
#pragma unroll 4
        for (int tc = 0; tc < NTC; tc++)
            s += g_pt[((size_t)n * NTC + tc) * (OC * VV) + idx];
        g_ybar[(size_t)n * OC * VV + idx] = s * (1.f / TT);
    }
}

// ============================================================================
// graphs: grid (NN, SS), 256 threads = 64 o2 x 4 k-slices, shfl reduction
// ============================================================================
__global__ __launch_bounds__(256)
void k_graphs(const float* __restrict__ W1, const float* __restrict__ b1,
              const float* __restrict__ W2, const float* __restrict__ b2,
              const int* __restrict__ node_type, float* __restrict__ gout) {
    const int n = blockIdx.x, s = blockIdx.y;
    const int tid   = threadIdx.x;
    const int slice = tid & 3;        // adjacent lanes = slices of same o2
    const int o2i   = tid >> 2;       // 0..63
    const int o2    = s * COUT + o2i;

    __shared__ float syb[OC * VV];    // 19.2 KB
    __shared__ int   stype[VV];

    {
        const float4* src = (const float4*)(g_ybar + (size_t)n * OC * VV);
        float4* dst = (float4*)syb;
        for (int i = tid; i < OC * VV / 4; i += 256) dst[i] = src[i];
    }
    const bool is64 = (node_type[1] == 0);
    if (tid < VV) stype[tid] = is64 ? node_type[2 * tid] : node_type[tid];
    __syncthreads();

    float x1[VV], x2[VV];
#pragma unroll
    for (int v = 0; v < VV; v++) { x1[v] = 0.f; x2[v] = 0.f; }

    const float* w1r = W1 + (size_t)o2 * OC + slice * 48;
    const float* w2r = W2 + (size_t)o2 * OC + slice * 48;
    const float* yb0 = &syb[slice * 48 * VV];
#pragma unroll 4
    for (int o = 0; o < 48; o++) {
        const float w1 = w1r[o], w2 = w2r[o];
        const float* yb = yb0 + o * VV;
#pragma unroll
        for (int v = 0; v < VV; v++) {
            x1[v] += w1 * yb[v];
            x2[v] += w2 * yb[v];
        }
    }

    // butterfly reduce across the 4 slices (adjacent lanes)
#pragma unroll
    for (int v = 0; v < VV; v++) {
        x1[v] += __shfl_xor_sync(0xffffffffu, x1[v], 1);
        x1[v] += __shfl_xor_sync(0xffffffffu, x1[v], 2);
        x2[v] += __shfl_xor_sync(0xffffffffu, x2[v], 1);
        x2[v] += __shfl_xor_sync(0xffffffffu, x2[v], 2);
    }

    if (slice == 0) {
        const float bb1 = b1[o2], bb2 = b2[o2];
        int cnt = 0;
        float sem = 0.f;
#pragma unroll
        for (int v = 0; v < VV; v++) {
            const float v1 = x1[v] + bb1;
            if (stype[v] == s) { sem += v1; cnt++; }
        }
        sem *= (1.f / (float)cnt);

        float* gp = gout + (size_t)n * (SS * COUT * VV) + (size_t)o2 * VV;
#pragma unroll
        for (int v = 0; v < VV; v++) gp[v] = sem - (x2[v] + bb2);
    }
}

__global__ void k_copyA(const float* __restrict__ A, float* __restrict__ dst) {
    int i = blockIdx.x * 256 + threadIdx.x;
    if (i < KK * VV * VV) dst[i] = A[i];
}

// ============================================================================
extern "C" void kernel_launch(void* const* d_in, const int* in_sizes, int n_in,
                              void* d_out, int out_size) {
    (void)in_sizes; (void)n_in; (void)out_size;
    const float* x  = (const float*)d_in[0];
    const float* A  = (const float*)d_in[1];
    const int*   nt = (const int*)  d_in[2];
    const float* Wc = (const float*)d_in[3];
    const float* bc = (const float*)d_in[4];
    const float* W1 = (const float*)d_in[5];
    const float* b1 = (const float*)d_in[6];
    const float* W2 = (const float*)d_in[7];
    const float* b2 = (const float*)d_in[8];

    float* out  = (float*)d_out;
    float* outA = out + (size_t)NN * COUT * TT * VV;   // 26,214,400
    float* outG = outA + KK * VV * VV;                 // + 1,875

    static int smem_set = 0;
    if (!smem_set) {
        cudaFuncSetAttribute(k_fused, cudaFuncAttributeMaxDynamicSharedMemorySize, SMEM_BYTES);
        smem_set = 1;
    }

    k_wt         <<<(OC * CIN + 255) / 256, 256>>>(Wc);
    k_fused      <<<dim3(NTC, NN), NTHR, SMEM_BYTES>>>(x, bc, A, out);
    k_ybar_reduce<<<NN, 256>>>();
    k_graphs     <<<dim3(NN, SS), 256>>>(W1, b1, W2, b2, nt, outG);
    k_copyA      <<<8, 256>>>(A, outA);
}